// round 13
// baseline (speedup 1.0000x reference)
#include <cuda_runtime.h>
#include <cuda_bf16.h>
#include <stdint.h>
#include <math.h>

// Problem constants
#define Bdim 8
#define Nseq 4096
#define Dmod 512
#define Hh   8
#define Rr   256
#define DP   64
#define BH   64          // Bdim*Hh
#define MT   32768       // Bdim*Nseq

// ---------------------------------------------------------------------------
// Scratch (module-static device memory)
// ---------------------------------------------------------------------------
__device__ __nv_bfloat16 g_xhi[(size_t)MT * Dmod];
__device__ __nv_bfloat16 g_xlo[(size_t)MT * Dmod];
__device__ __nv_bfloat16 g_whi[4 * Dmod * Dmod];   // [z][n][k] transposed
__device__ __nv_bfloat16 g_wlo[4 * Dmod * Dmod];
__device__ __nv_bfloat16 g_ehi[(size_t)Hh * Nseq * Rr];
__device__ __nv_bfloat16 g_elo[(size_t)Hh * Nseq * Rr];
__device__ __nv_bfloat16 g_fhi[(size_t)Hh * Nseq * Rr];
__device__ __nv_bfloat16 g_flo[(size_t)Hh * Nseq * Rr];
__device__ __nv_bfloat16 g_qhi[(size_t)BH * Nseq * DP];
__device__ __nv_bfloat16 g_qlo[(size_t)BH * Nseq * DP];
__device__ __nv_bfloat16 g_khi[(size_t)BH * Nseq * DP];
__device__ __nv_bfloat16 g_klo[(size_t)BH * Nseq * DP];
__device__ __nv_bfloat16 g_vhi[(size_t)BH * Nseq * DP];
__device__ __nv_bfloat16 g_vlo[(size_t)BH * Nseq * DP];
__device__ float         g_part[(size_t)8 * 1048576];   // [ef][ksplit][bh][256][64]
__device__ __nv_bfloat16 g_kphi[(size_t)BH * Rr * DP];
__device__ __nv_bfloat16 g_kplo[(size_t)BH * Rr * DP];
__device__ __nv_bfloat16 g_vphi[(size_t)BH * Rr * DP];
__device__ __nv_bfloat16 g_vplo[(size_t)BH * Rr * DP];
__device__ __nv_bfloat16 g_chi[(size_t)MT * Dmod];
__device__ __nv_bfloat16 g_clo[(size_t)MT * Dmod];

// ---------------------------------------------------------------------------
// PTX helpers (compute_103-safe)
// ---------------------------------------------------------------------------
__device__ __forceinline__ uint32_t smem_u32(const void* p) {
    uint32_t a;
    asm("{ .reg .u64 t; cvta.to.shared.u64 t, %1; cvt.u32.u64 %0, t; }" : "=r"(a) : "l"(p));
    return a;
}
__device__ __forceinline__ void cpa16(uint32_t dst, const void* src) {
    asm volatile("cp.async.cg.shared.global [%0], [%1], 16;" :: "r"(dst), "l"(src));
}
__device__ __forceinline__ void ldsm4(uint32_t& r0, uint32_t& r1, uint32_t& r2,
                                      uint32_t& r3, uint32_t addr) {
    asm volatile("ldmatrix.sync.aligned.m8n8.x4.shared.b16 {%0,%1,%2,%3}, [%4];"
                 : "=r"(r0), "=r"(r1), "=r"(r2), "=r"(r3) : "r"(addr));
}
__device__ __forceinline__ void ldsm4t(uint32_t& r0, uint32_t& r1, uint32_t& r2,
                                       uint32_t& r3, uint32_t addr) {
    asm volatile("ldmatrix.sync.aligned.m8n8.x4.trans.shared.b16 {%0,%1,%2,%3}, [%4];"
                 : "=r"(r0), "=r"(r1), "=r"(r2), "=r"(r3) : "r"(addr));
}
__device__ __forceinline__ void mma16816(float* c, uint32_t a0, uint32_t a1,
                                         uint32_t a2, uint32_t a3,
                                         uint32_t b0, uint32_t b1) {
    asm volatile(
        "mma.sync.aligned.m16n8k16.row.col.f32.bf16.bf16.f32 "
        "{%0,%1,%2,%3}, {%4,%5,%6,%7}, {%8,%9}, {%0,%1,%2,%3};"
        : "+f"(c[0]), "+f"(c[1]), "+f"(c[2]), "+f"(c[3])
        : "r"(a0), "r"(a1), "r"(a2), "r"(a3), "r"(b0), "r"(b1));
}
__device__ __forceinline__ uint32_t fsplit2(float a, float b, uint32_t& lo) {
    __nv_bfloat16 ha = __float2bfloat16(a), hb = __float2bfloat16(b);
    __nv_bfloat16 la = __float2bfloat16(a - __bfloat162float(ha));
    __nv_bfloat16 lb = __float2bfloat16(b - __bfloat162float(hb));
    __nv_bfloat162 H = __halves2bfloat162(ha, hb);
    __nv_bfloat162 L = __halves2bfloat162(la, lb);
    lo = *(uint32_t*)&L;
    return *(uint32_t*)&H;
}
// fast exp2 via degree-6 poly (rel err ~1.6e-5) — FMA pipe, no MUFU
__device__ __forceinline__ float fexp2(float x) {
    x = fmaxf(x, -120.f);
    float xi = floorf(x);
    float f = x - xi;
    float p = 1.54035304e-4f;
    p = fmaf(p, f, 1.33335581e-3f);
    p = fmaf(p, f, 9.61812911e-3f);
    p = fmaf(p, f, 5.55041087e-2f);
    p = fmaf(p, f, 2.40226507e-1f);
    p = fmaf(p, f, 6.93147181e-1f);
    p = fmaf(p, f, 1.0f);
    return p * __int_as_float(((int)xi + 127) << 23);
}

// ---------------------------------------------------------------------------
// convw + x-split: grid-strided x fp32->hi/lo split prologue, then
// transpose + split weights: g_w{hi,lo}[z][n][k] = split(w_z[k][n])
// grid (16,16,4), block (32,8) = 256 threads, 1024 blocks.
// ---------------------------------------------------------------------------
__global__ __launch_bounds__(256) void convw_kernel(
    const float* __restrict__ x,
    const float* __restrict__ wq, const float* __restrict__ wk,
    const float* __restrict__ wv, const float* __restrict__ wd)
{
    const int t = threadIdx.y * 32 + threadIdx.x;
    // ---- x split prologue (grid-strided over all 1024 blocks) ----
    {
        const size_t gid = ((size_t)blockIdx.z * 16 + blockIdx.y) * 16 + blockIdx.x;
        const size_t NV = (size_t)MT * Dmod / 4;
        for (size_t v = gid * 256 + t; v < NV; v += (size_t)1024 * 256) {
            size_t i = v * 4;
            float4 val = *(const float4*)(x + i);
            uint32_t l0, l1;
            uint32_t h0 = fsplit2(val.x, val.y, l0);
            uint32_t h1 = fsplit2(val.z, val.w, l1);
            *(uint32_t*)(g_xhi + i)     = h0;
            *(uint32_t*)(g_xhi + i + 2) = h1;
            *(uint32_t*)(g_xlo + i)     = l0;
            *(uint32_t*)(g_xlo + i + 2) = l1;
        }
    }
    // ---- weight transpose + split ----
    const int z = blockIdx.z;
    const float* w = (z == 0) ? wq : (z == 1) ? wk : (z == 2) ? wv : wd;
    __shared__ float tile[32][33];
    const int k0 = blockIdx.x * 32, n0 = blockIdx.y * 32;
    const int tx = threadIdx.x, ty = threadIdx.y;
#pragma unroll
    for (int i = 0; i < 4; i++)
        tile[ty + i * 8][tx] = w[(size_t)(k0 + ty + i * 8) * Dmod + n0 + tx];
    __syncthreads();
#pragma unroll
    for (int i = 0; i < 4; i++) {
        float xv = tile[tx][ty + i * 8];
        __nv_bfloat16 h = __float2bfloat16(xv);
        size_t o = (size_t)z * Dmod * Dmod + (size_t)(n0 + ty + i * 8) * Dmod + k0 + tx;
        g_whi[o] = h;
        g_wlo[o] = __float2bfloat16(xv - __bfloat162float(h));
    }
}

// ---------------------------------------------------------------------------
// mma.sync split-bf16 GEMM: C(128x128) = A(Mx512) @ W(512x512)
// EXACT R10 version (proven best). mode 0 folds the E/F split prologue.
// ---------------------------------------------------------------------------
__device__ __forceinline__ void issue_chunk(
    const __nv_bfloat16* __restrict__ Ahi, const __nv_bfloat16* __restrict__ Alo,
    const __nv_bfloat16* __restrict__ Bhi, const __nv_bfloat16* __restrict__ Blo,
    uint32_t sb, int stage, int c, int t, int rowBase, int colBase)
{
    const int k0 = c * 32;
#pragma unroll
    for (int u = 0; u < 2; u++) {
        int id = t + u * 256;
        int row = id >> 2, k8 = id & 3;
        size_t gA = (size_t)(rowBase + row) * Dmod + k0 + k8 * 8;
        size_t gB = (size_t)(colBase + row) * Dmod + k0 + k8 * 8;
        uint32_t so = sb + stage * 40960 + row * 80 + k8 * 16;
        cpa16(so + 0,     Ahi + gA);
        cpa16(so + 10240, Alo + gA);
        cpa16(so + 20480, Bhi + gB);
        cpa16(so + 30720, Blo + gB);
    }
    asm volatile("cp.async.commit_group;" ::: "memory");
}

__global__ __launch_bounds__(256) void gemm_kernel(
    const __nv_bfloat16* __restrict__ Ahi, const __nv_bfloat16* __restrict__ Alo,
    const float* __restrict__ bias, float* __restrict__ dOut,
    const float* __restrict__ Esrc, const float* __restrict__ Fsrc, int mode)
{
    extern __shared__ __align__(128) char smx[];
    const uint32_t sb = smem_u32(smx);
    const int t = threadIdx.x;
    const int lane = t & 31, wid = t >> 5;
    const int warpM = wid & 3, warpN = wid >> 2;
    const int z   = (mode == 0) ? (blockIdx.x >> 2) : 3;
    const int col = (mode == 0) ? (blockIdx.x & 3) : blockIdx.x;
    const int rowBase = blockIdx.y * 128;
    const int colBase = col * 128;
    const __nv_bfloat16* Bhi = g_whi + (size_t)z * Dmod * Dmod;
    const __nv_bfloat16* Blo = g_wlo + (size_t)z * Dmod * Dmod;

    // ---- folded E/F split prologue (mode 0 only) ----
    if (mode == 0) {
        const size_t NV = (size_t)Hh * Nseq * Rr / 4;
        const size_t gsz = (size_t)12 * gridDim.y * 256;
        for (size_t v = (size_t)(blockIdx.y * 12 + blockIdx.x) * 256 + t;
             v < 2 * NV; v += gsz) {
            const float* src;
            __nv_bfloat16 *hi, *lo;
            size_t i;
            if (v < NV) { src = Esrc; hi = g_ehi; lo = g_elo; i = v * 4; }
            else        { src = Fsrc; hi = g_fhi; lo = g_flo; i = (v - NV) * 4; }
            float4 val = *(const float4*)(src + i);
            uint32_t l0, l1;
            uint32_t h0 = fsplit2(val.x, val.y, l0);
            uint32_t h1 = fsplit2(val.z, val.w, l1);
            *(uint32_t*)(hi + i)     = h0;
            *(uint32_t*)(hi + i + 2) = h1;
            *(uint32_t*)(lo + i)     = l0;
            *(uint32_t*)(lo + i + 2) = l1;
        }
    }

    float acc[2][8][4];
#pragma unroll
    for (int mi = 0; mi < 2; mi++)
#pragma unroll
        for (int nf = 0; nf < 8; nf++)
#pragma unroll
            for (int j = 0; j < 4; j++) acc[mi][nf][j] = 0.f;

    issue_chunk(Ahi, Alo, Bhi, Blo, sb, 0, 0, t, rowBase, colBase);

    for (int c = 0; c < 16; c++) {
        if (c < 15) {
            issue_chunk(Ahi, Alo, Bhi, Blo, sb, (c + 1) & 1, c + 1, t, rowBase, colBase);
            asm volatile("cp.async.wait_group 1;" ::: "memory");
        } else {
            asm volatile("cp.async.wait_group 0;" ::: "memory");
        }
        __syncthreads();

        const uint32_t sA = sb + (c & 1) * 40960;
#pragma unroll
        for (int kk = 0; kk < 2; kk++) {
            uint32_t ahi[2][4], alo[2][4], bhi[16], blo[16];
#pragma unroll
            for (int mi = 0; mi < 2; mi++) {
                int row = warpM * 32 + mi * 16 + (lane & 15);
                int colk = kk * 16 + (lane >> 4) * 8;
                uint32_t ao = row * 80 + colk * 2;
                ldsm4(ahi[mi][0], ahi[mi][1], ahi[mi][2], ahi[mi][3], sA + ao);
                ldsm4(alo[mi][0], alo[mi][1], alo[mi][2], alo[mi][3], sA + 10240 + ao);
            }
#pragma unroll
            for (int g = 0; g < 4; g++) {
                int row = warpN * 64 + g * 16 + (lane & 7) + (lane >> 4) * 8;
                int colk = kk * 16 + ((lane >> 3) & 1) * 8;
                uint32_t bo = row * 80 + colk * 2;
                ldsm4(bhi[g * 4], bhi[g * 4 + 1], bhi[g * 4 + 2], bhi[g * 4 + 3],
                      sA + 20480 + bo);
                ldsm4(blo[g * 4], blo[g * 4 + 1], blo[g * 4 + 2], blo[g * 4 + 3],
                      sA + 30720 + bo);
            }
#pragma unroll
            for (int mi = 0; mi < 2; mi++)
#pragma unroll
                for (int nf = 0; nf < 8; nf++) {
                    int g = nf >> 1, j = nf & 1;
                    uint32_t b0 = bhi[g * 4 + j * 2], b1 = bhi[g * 4 + j * 2 + 1];
                    uint32_t l0 = blo[g * 4 + j * 2], l1 = blo[g * 4 + j * 2 + 1];
                    mma16816(acc[mi][nf], ahi[mi][0], ahi[mi][1], ahi[mi][2], ahi[mi][3], b0, b1);
                    mma16816(acc[mi][nf], ahi[mi][0], ahi[mi][1], ahi[mi][2], ahi[mi][3], l0, l1);
                    mma16816(acc[mi][nf], alo[mi][0], alo[mi][1], alo[mi][2], alo[mi][3], b0, b1);
                }
        }
        __syncthreads();
    }

    const int r0base = rowBase + warpM * 32 + (lane >> 2);
    if (mode == 0) {
        __nv_bfloat16* oh = (z == 0) ? g_qhi : (z == 1) ? g_khi : g_vhi;
        __nv_bfloat16* ol = (z == 0) ? g_qlo : (z == 1) ? g_klo : g_vlo;
        const int h = (colBase + warpN * 64) >> 6;
#pragma unroll
        for (int mi = 0; mi < 2; mi++) {
            int r0 = r0base + mi * 16;
            int bb = r0 >> 12, n = r0 & 4095;
            size_t rb0 = ((size_t)(bb * Hh + h) * Nseq + n) * DP;
            size_t rb1 = rb0 + 8 * DP;
#pragma unroll
            for (int nf = 0; nf < 8; nf++) {
                int d = nf * 8 + (lane & 3) * 2;
                uint32_t lo0, lo1;
                uint32_t hi0 = fsplit2(acc[mi][nf][0], acc[mi][nf][1], lo0);
                uint32_t hi1 = fsplit2(acc[mi][nf][2], acc[mi][nf][3], lo1);
                *(uint32_t*)(oh + rb0 + d) = hi0;
                *(uint32_t*)(ol + rb0 + d) = lo0;
                *(uint32_t*)(oh + rb1 + d) = hi1;
                *(uint32_t*)(ol + rb1 + d) = lo1;
            }
        }
    } else {
        const int col0 = colBase + warpN * 64;
#pragma unroll
        for (int mi = 0; mi < 2; mi++) {
            int r0 = r0base + mi * 16;
            float* p0 = dOut + (size_t)r0 * Dmod + col0;
            float* p1 = p0 + 8 * Dmod;
#pragma unroll
            for (int nf = 0; nf < 8; nf++) {
                int d = nf * 8 + (lane & 3) * 2;
                float2 bi = *(const float2*)(bias + col0 + d);
                *(float2*)(p0 + d) = make_float2(acc[mi][nf][0] + bi.x,
                                                 acc[mi][nf][1] + bi.y);
                *(float2*)(p1 + d) = make_float2(acc[mi][nf][2] + bi.x,
                                                 acc[mi][nf][3] + bi.y);
            }
        }
    }
}

// ---------------------------------------------------------------------------
// proj: EXACT R10 version.
// ---------------------------------------------------------------------------
#define PEHI 0
#define PELO 16896
#define PKHI 33792
#define PKLO 38400
#define PSTG 43008

__global__ __launch_bounds__(256) void proj_kernel()
{
    extern __shared__ __align__(128) char smx[];
    const uint32_t sb = smem_u32(smx);
    const int t = threadIdx.x, lane = t & 31, wid = t >> 5;
    const int warpM = wid & 3, warpN = wid >> 2;
    const int bh = blockIdx.x & 63, ef = blockIdx.x >> 6;
    const int ks = blockIdx.y;
    const int h = bh & 7;

    const __nv_bfloat16* Eh = (ef ? g_fhi : g_ehi) + (size_t)h * Nseq * Rr;
    const __nv_bfloat16* El = (ef ? g_flo : g_elo) + (size_t)h * Nseq * Rr;
    const __nv_bfloat16* Kh = (ef ? g_vhi : g_khi) + (size_t)bh * Nseq * DP;
    const __nv_bfloat16* Kl = (ef ? g_vlo : g_klo) + (size_t)bh * Nseq * DP;
    float* part = g_part + (((size_t)ef * 4 + ks) * 64 + bh) * 16384;

    const int nBase = ks * 1024;
    const int r0 = warpM * 64, d0 = warpN * 32;

    float acc[16][4];
#pragma unroll
    for (int i = 0; i < 16; i++)
#pragma unroll
        for (int j = 0; j < 4; j++) acc[i][j] = 0.f;

    auto issue = [&](int stage, int c) {
        const int n0 = nBase + c * 32;
        const uint32_t so = sb + stage * PSTG;
#pragma unroll
        for (int u = 0; u < 4; u++) {
            int id = u * 256 + t;
            int row = id >> 5, seg = id & 31;
            cpa16(so + PEHI + row * 528 + seg * 16, Eh + (size_t)(n0 + row) * Rr + seg * 8);
            cpa16(so + PELO + row * 528 + seg * 16, El + (size_t)(n0 + row) * Rr + seg * 8);
        }
        {
            int row = t >> 3, seg = t & 7;
            cpa16(so + PKHI + row * 144 + seg * 16, Kh + (size_t)(n0 + row) * DP + seg * 8);
            cpa16(so + PKLO + row * 144 + seg * 16, Kl + (size_t)(n0 + row) * DP + seg * 8);
        }
        asm volatile("cp.async.commit_group;" ::: "memory");
    };

    issue(0, 0);
    for (int c = 0; c < 32; c++) {
        if (c < 31) {
            issue((c + 1) & 1, c + 1);
            asm volatile("cp.async.wait_group 1;" ::: "memory");
        } else {
            asm volatile("cp.async.wait_group 0;" ::: "memory");
        }
        __syncthreads();

        const uint32_t st = sb + (c & 1) * PSTG;
#pragma unroll
        for (int kk = 0; kk < 2; kk++) {
            uint32_t ah[4][4], al[4][4];
            const int krA = kk * 16 + (lane & 7) + ((lane >> 4) & 1) * 8;
#pragma unroll
            for (int mf = 0; mf < 4; mf++) {
                uint32_t off = krA * 528 + (r0 + mf * 16 + ((lane >> 3) & 1) * 8) * 2;
                ldsm4t(ah[mf][0], ah[mf][1], ah[mf][2], ah[mf][3], st + PEHI + off);
                ldsm4t(al[mf][0], al[mf][1], al[mf][2], al[mf][3], st + PELO + off);
            }
            const int krB = kk * 16 + (lane & 7) + ((lane >> 3) & 1) * 8;
#pragma unroll
            for (int g2 = 0; g2 < 2; g2++) {
                uint32_t off = krB * 144 + (d0 + g2 * 16 + ((lane >> 4) & 1) * 8) * 2;
                uint32_t b0, b1, b2, b3, l0, l1, l2, l3;
                ldsm4t(b0, b1, b2, b3, st + PKHI + off);
                ldsm4t(l0, l1, l2, l3, st + PKLO + off);
#pragma unroll
                for (int mf = 0; mf < 4; mf++) {
                    float* c0 = acc[mf * 4 + g2 * 2];
                    float* c1 = acc[mf * 4 + g2 * 2 + 1];
                    mma16816(c0, ah[mf][0], ah[mf][1], ah[mf][2], ah[mf][3], b0, b1);
                    mma16816(c1, ah[mf][0], ah[mf][1], ah[mf][2], ah[mf][3], b2, b3);
                    mma16816(c0, ah[mf][0], ah[mf][1], ah[mf][2], ah[mf][3], l0, l1);
                    mma16816(c1, ah[mf][0], ah[mf][1], ah[mf][2], ah[mf][3], l2, l3);
                    mma16816(c0, al[mf][0], al[mf][1], al[mf][2], al[mf][3], b0, b1);
                    mma16816(c1, al[mf][0], al[mf][1], al[mf][2], al[mf][3], b2, b3);
                }
            }
        }
        __syncthreads();
    }

#pragma unroll
    for (int mf = 0; mf < 4; mf++) {
        int r = r0 + mf * 16 + (lane >> 2);
#pragma unroll
        for (int f = 0; f < 4; f++) {
            int d = d0 + f * 8 + (lane & 3) * 2;
            *(float2*)(part + r * 64 + d) =
                make_float2(acc[mf * 4 + f][0], acc[mf * 4 + f][1]);
            *(float2*)(part + (r + 8) * 64 + d) =
                make_float2(acc[mf * 4 + f][2], acc[mf * 4 + f][3]);
        }
    }
}

// reduce 4 K-split partials -> split to bf16 hi/lo kp/vp. grid (1024, 2).
__global__ __launch_bounds__(256) void reduce_kernel()
{
    const int ef = blockIdx.y;
    size_t base = ((size_t)blockIdx.x * 256 + threadIdx.x) * 4;
    const float* p = g_part + (size_t)ef * 4194304 + base;
    float4 s0 = *(const float4*)(p);
    float4 s1 = *(const float4*)(p + 1048576);
    float4 s2 = *(const float4*)(p + 2097152);
    float4 s3 = *(const float4*)(p + 3145728);
    float a = s0.x + s1.x + s2.x + s3.x;
    float b = s0.y + s1.y + s2.y + s3.y;
    float c = s0.z + s1.z + s2.z + s3.z;
    float d = s0.w + s1.w + s2.w + s3.w;
    __nv_bfloat16* hi = ef ? g_vphi : g_kphi;
    __nv_bfloat16* lo = ef ? g_vplo : g_kplo;
    uint32_t l0, l1;
    uint32_t h0 = fsplit2(a, b, l0);
    uint32_t h1 = fsplit2(c, d, l1);
    *(uint32_t*)(hi + base)     = h0;
    *(uint32_t*)(hi + base + 2) = h1;
    *(uint32_t*)(lo + base)     = l0;
    *(uint32_t*)(lo + base + 2) = l1;
}

// ---------------------------------------------------------------------------
// attn: per block one (b,h) + FOUR 128-row Q tiles (flash-style pipeline).
// kp/vp loaded once per block; Q(t+1) prefetched during GEMM2 of tile t.
// grid (64, 8). smem layout unchanged (184320 B).
// ---------------------------------------------------------------------------
#define AQHI 0
#define AQLO 18432
#define AKPHI 36864
#define AKPLO 73728
#define AVPHI 110592
#define AVPLO 147456
#define NTILE 4

__global__ __launch_bounds__(256) void attn_kernel()
{
    extern __shared__ __align__(128) char smx[];
    const uint32_t sb = smem_u32(smx);
    const int t = threadIdx.x, lane = t & 31, w = t >> 5;
    const int bh = blockIdx.x;
    const int tileBase = blockIdx.y * NTILE;

    const __nv_bfloat16* kh = g_kphi + (size_t)bh * Rr * DP;
    const __nv_bfloat16* kl = g_kplo + (size_t)bh * Rr * DP;
    const __nv_bfloat16* vh = g_vphi + (size_t)bh * Rr * DP;
    const __nv_bfloat16* vl = g_vplo + (size_t)bh * Rr * DP;

    auto loadQ = [&](int tile) {
        const __nv_bfloat16* qh = g_qhi + ((size_t)bh * Nseq + tile * 128) * DP;
        const __nv_bfloat16* ql = g_qlo + ((size_t)bh * Nseq + tile * 128) * DP;
#pragma unroll
        for (int u = 0; u < 4; u++) {
            int id = u * 256 + t, row = id >> 3, seg = id & 7;
            cpa16(sb + AQHI + row * 144 + seg * 16, qh + row * 64 + seg * 8);
            cpa16(sb + AQLO + row * 144 + seg * 16, ql + row * 64 + seg * 8);
        }
        asm volatile("cp.async.commit_group;" ::: "memory");
    };

    // group0: kp + Q(tile0); group1: vp
#pragma unroll
    for (int u = 0; u < 8; u++) {
        int id = u * 256 + t, row = id >> 3, seg = id & 7;
        cpa16(sb + AKPHI + row * 144 + seg * 16, kh + row * 64 + seg * 8);
        cpa16(sb + AKPLO + row * 144 + seg * 16, kl + row * 64 + seg * 8);
    }
    {
        const __nv_bfloat16* qh = g_qhi + ((size_t)bh * Nseq + tileBase * 128) * DP;
        const __nv_bfloat16* ql = g_qlo + ((size_t)bh * Nseq + tileBase * 128) * DP;
#pragma unroll
        for (int u = 0; u < 4; u++) {
            int id = u * 256 + t, row = id >> 3, seg = id & 7;
            cpa16(sb + AQHI + row * 144 + seg * 16, qh + row * 64 + seg * 8);
            cpa16(sb + AQLO + row * 144 + seg * 16, ql + row * 64 + seg * 8);
        }
    }
    asm volatile("cp.async.commit_group;" ::: "memory");
#pragma unroll
    for (int u = 0; u < 8; u++) {
        int id = u * 256 + t, row = id >> 3, seg = id & 7;
        cpa16(sb + AVPHI + row * 144 + seg * 16, vh + row * 64 + seg * 8);
        cpa16(sb + AVPLO + row * 144 + seg * 16, vl + row * 64 + seg * 8);
    }
    asm volatile("cp.async.commit_group;" ::: "memory");

    const int m0 = w * 16;
    const float C = 0.125f * 1.4426950408889634f;
    const int b = bh >> 3, h = bh & 7;

    for (int tt = 0; tt < NTILE; tt++) {
        const int tile = tileBase + tt;
        if (tt == 0) {
            // kp + Q0 ready (vp may still be in flight)
            asm volatile("cp.async.wait_group 1;" ::: "memory");
        } else {
            asm volatile("cp.async.wait_group 0;" ::: "memory");
        }
        __syncthreads();

        // ---- GEMM1: scores[16][256] ----
        float c[32][4];
#pragma unroll
        for (int i = 0; i < 32; i++)
#pragma unroll
            for (int j = 0; j < 4; j++) c[i][j] = 0.f;

#pragma unroll
        for (int kk = 0; kk < 4; kk++) {
            uint32_t ah0, ah1, ah2, ah3, al0, al1, al2, al3;
            {
                uint32_t ar = (m0 + (lane & 15)) * 144 + (kk * 16 + (lane >> 4) * 8) * 2;
                ldsm4(ah0, ah1, ah2, ah3, sb + AQHI + ar);
                ldsm4(al0, al1, al2, al3, sb + AQLO + ar);
            }
#pragma unroll
            for (int nb = 0; nb < 16; nb++) {
                uint32_t br = (nb * 16 + (lane & 7) + ((lane >> 4) & 1) * 8) * 144
                            + (kk * 16 + ((lane >> 3) & 1) * 8) * 2;
                uint32_t b0, b1, b2, b3, l0, l1, l2, l3;
                ldsm4(b0, b1, b2, b3, sb + AKPHI + br);
                ldsm4(l0, l1, l2, l3, sb + AKPLO + br);
                mma16816(c[2 * nb],     ah0, ah1, ah2, ah3, b0, b1);
                mma16816(c[2 * nb + 1], ah0, ah1, ah2, ah3, b2, b3);
                mma16816(c[2 * nb],     ah0, ah1, ah2, ah3, l0, l1);
                mma16816(c[2 * nb + 1], ah0, ah1, ah2, ah3, l2, l3);
                mma16816(c[2 * nb],     al0, al1, al2, al3, b0, b1);
                mma16816(c[2 * nb + 1], al0, al1, al2, al3, b2, b3);
            }
        }

        // ---- softmax ----
        float mx0 = -1e30f, mx1 = -1e30f;
#pragma unroll
        for (int f = 0; f < 32; f++) {
            mx0 = fmaxf(mx0, fmaxf(c[f][0], c[f][1]));
            mx1 = fmaxf(mx1, fmaxf(c[f][2], c[f][3]));
        }
        mx0 = fmaxf(mx0, __shfl_xor_sync(0xffffffffu, mx0, 1));
        mx0 = fmaxf(mx0, __shfl_xor_sync(0xffffffffu, mx0, 2));
        mx1 = fmaxf(mx1, __shfl_xor_sync(0xffffffffu, mx1, 1));
        mx1 = fmaxf(mx1, __shfl_xor_sync(0xffffffffu, mx1, 2));
        float s0 = 0.f, s1 = 0.f;
#pragma unroll
        for (int f = 0; f < 32; f++) {
            c[f][0] = fexp2((c[f][0] - mx0) * C);
            c[f][1] = fexp2((c[f][1] - mx0) * C);
            c[f][2] = fexp2((c[f][2] - mx1) * C);
            c[f][3] = fexp2((c[f][3] - mx1) * C);
            s0 += c[f][0] + c[f][1];
            s1 += c[f][2] + c[f][3];
        }
        s0 += __shfl_xor_sync(0xffffffffu, s0, 1);
        s0 += __shfl_xor_sync(0xffffffffu, s0, 2);
        s1 += __shfl_xor_sync(0xffffffffu, s1, 1);
        s1 += __shfl_xor_sync(0xffffffffu, s1, 2);
        const float inv0 = 1.f / s0, inv1 = 1.f / s1;

        uint32_t phi[64], plo[64];
#pragma unroll
        for (int f = 0; f < 32; f++) {
            float p0 = c[f][0] * inv0, p1 = c[f][1] * inv0;
            float p2 = c[f][2] * inv1, p3 = c[f][3] * inv1;
            int base = (f >> 1) * 4 + (f & 1) * 2;
            uint32_t lo0, lo1;
            phi[base]     = fsplit2(p0, p1, lo0);
            phi[base + 1] = fsplit2(p2, p3, lo1);
            plo[base]     = lo0;
            plo[base + 1] = lo1;
        }

        // all warps done reading Q smem -> safe to prefetch next Q
        __syncthreads();
        if (tt + 1 < NTILE) loadQ(tile + 1);
        if (tt == 0) {
            // vp must be resident before GEMM2 (leaves Q prefetch pending)
            asm volatile("cp.async.wait_group 1;" ::: "memory");
            __syncthreads();
        }

        // ---- GEMM2: out[16][64] = P @ vp ----
        float o[8][4];
#pragma unroll
        for (int i = 0; i < 8; i++)
#pragma unroll
            for (int j = 0; j < 4; j++) o[i][j] = 0.f;

#pragma unroll
        for (int ks = 0; ks < 16; ks++) {
            uint32_t A0 = phi[ks * 4], A1 = phi[ks * 4 + 1];
            uint32_t A2 = phi[ks * 4 + 2], A3 = phi[ks * 4 + 3];
            uint32_t L0 = plo[ks * 4], L1 = plo[ks * 4 + 1];
            uint32_t L2 = plo[ks * 4 + 2], L3 = plo[ks * 4 + 3];
            const int krB = ks * 16 + (lane & 7) + ((lane >> 3) & 1) * 8;
#pragma unroll
            for (int g2 = 0; g2 < 4; g2++) {
                uint32_t off = krB * 144 + (g2 * 16 + ((lane >> 4) & 1) * 8) * 2;
                uint32_t b0, b1, b2, b3, l0, l1, l2, l3;
                ldsm4t(b0, b1, b2, b3, sb + AVPHI + off);
                ldsm4t(l0, l1, l2, l3, sb + AVPLO + off);
                mma16816(o[g2 * 2],     A0, A1, A2, A3, b0, b1);
                mma16816(o[g2 * 2 + 1], A0, A1, A2, A3, b2, b3);
                mma16816(o[g2 * 2],     A0, A1, A2, A3, l0, l1);
                mma16816(o[g2 * 2 + 1], A0, A1, A2, A3, l2, l3);
                mma16816(o[g2 * 2],     L0, L1, L2, L3, b0, b1);
                mma16816(o[g2 * 2 + 1], L0, L1, L2, L3, b2, b3);
            }
        }

        // ---- epilogue: split to bf16 hi/lo, concat layout ----
        const int n0 = tile * 128 + m0 + (lane >> 2);
#pragma unroll
        for (int f = 0; f < 8; f++) {
            int d = f * 8 + (lane & 3) * 2;
            size_t i0 = (size_t)(b * Nseq + n0) * Dmod + h * 64 + d;
            size_t i1 = i0 + (size_t)8 * Dmod;
            uint32_t lo0, lo1;
            uint32_t hi0 = fsplit2(o[f][0], o[f][1], lo0);
            uint32_t hi1 = fsplit2(o[f][2], o[f][3], lo1);
            *(uint32_t*)(g_chi + i0) = hi0;
            *(uint32_t*)(g_clo + i0) = lo0;
            *(uint32_t*)(g_chi + i1) = hi1;
            *(uint32_t*)(g_clo + i1) = lo1;
        }
    }
}

// ---------------------------------------------------------------------------
extern "C" void kernel_launch(void* const* d_in, const int* in_sizes, int n_in,
                              void* d_out, int out_size)
{
    const float* x  = (const float*)d_in[0];
    const float* wq = (const float*)d_in[1];
    const float* wk = (const float*)d_in[2];
    const float* wv = (const float*)d_in[3];
    const float* E  = (const float*)d_in[4];
    const float* F  = (const float*)d_in[5];
    const float* wd = (const float*)d_in[6];
    const float* bd = (const float*)d_in[7];
    float* out = (float*)d_out;

    __nv_bfloat16 *xhi, *xlo, *chi, *clo;
    cudaGetSymbolAddress((void**)&xhi, g_xhi);
    cudaGetSymbolAddress((void**)&xlo, g_xlo);
    cudaGetSymbolAddress((void**)&chi, g_chi);
    cudaGetSymbolAddress((void**)&clo, g_clo);

    cudaFuncSetAttribute(gemm_kernel,
                         cudaFuncAttributeMaxDynamicSharedMemorySize, 81920);
    cudaFuncSetAttribute(proj_kernel,
                         cudaFuncAttributeMaxDynamicSharedMemorySize, 86016);
    cudaFuncSetAttribute(attn_kernel,
                         cudaFuncAttributeMaxDynamicSharedMemorySize, 184320);

    // x split + weight transpose/split in one launch
    convw_kernel<<<dim3(16, 16, 4), dim3(32, 8)>>>(x, wq, wk, wv, wd);

    // QKV -> bf16 hi/lo q,k,v; also performs E/F split as overlapped prologue
    gemm_kernel<<<dim3(12, MT / 128), 256, 81920>>>(xhi, xlo, nullptr, nullptr, E, F, 0);

    // low-rank projections -> partials -> kp/vp hi/lo
    proj_kernel<<<dim3(128, 4), 256, 86016>>>();
    reduce_kernel<<<dim3(1024, 2), 256>>>();

    // fused attention -> concat hi/lo (4 tiles per block, pipelined)
    attn_kernel<<<dim3(BH, Nseq / 128 / NTILE), 256, 184320>>>();

    // output dense
    gemm_kernel<<<dim3(4, MT / 128), 256, 81920>>>(chi, clo, bd, out, nullptr, nullptr, 1);
}

// round 17
// speedup vs baseline: 1.3435x; 1.3435x over previous
#include <cuda_runtime.h>
#include <cuda_fp16.h>
#include <stdint.h>
#include <math.h>

// Problem constants
#define Bdim 8
#define Nseq 4096
#define Dmod 512
#define Hh   8
#define Rr   256
#define DP   64
#define BH   64          // Bdim*Hh
#define MT   32768       // Bdim*Nseq

// ---------------------------------------------------------------------------
// Scratch (module-static device memory) — fp16 asymmetric split:
// A-side operands keep hi only; B-side operands keep hi+lo.
// ---------------------------------------------------------------------------
__device__ __half g_xhi[(size_t)MT * Dmod];
__device__ __half g_whi[4 * Dmod * Dmod];   // [z][n][k] transposed
__device__ __half g_wlo[4 * Dmod * Dmod];
__device__ __half g_ehi[(size_t)Hh * Nseq * Rr];
__device__ __half g_fhi[(size_t)Hh * Nseq * Rr];
__device__ __half g_qhi[(size_t)BH * Nseq * DP];
__device__ __half g_khi[(size_t)BH * Nseq * DP];
__device__ __half g_klo[(size_t)BH * Nseq * DP];
__device__ __half g_vhi[(size_t)BH * Nseq * DP];
__device__ __half g_vlo[(size_t)BH * Nseq * DP];
__device__ float  g_part[(size_t)8 * 1048576];   // [ef][ksplit][bh][256][64]
__device__ __half g_kphi[(size_t)BH * Rr * DP];
__device__ __half g_kplo[(size_t)BH * Rr * DP];
__device__ __half g_vphi[(size_t)BH * Rr * DP];
__device__ __half g_vplo[(size_t)BH * Rr * DP];
__device__ __half g_chi[(size_t)MT * Dmod];

// ---------------------------------------------------------------------------
// PTX helpers (compute_103-safe)
// ---------------------------------------------------------------------------
__device__ __forceinline__ uint32_t smem_u32(const void* p) {
    uint32_t a;
    asm("{ .reg .u64 t; cvta.to.shared.u64 t, %1; cvt.u32.u64 %0, t; }" : "=r"(a) : "l"(p));
    return a;
}
__device__ __forceinline__ void cpa16(uint32_t dst, const void* src) {
    asm volatile("cp.async.cg.shared.global [%0], [%1], 16;" :: "r"(dst), "l"(src));
}
__device__ __forceinline__ void ldsm4(uint32_t& r0, uint32_t& r1, uint32_t& r2,
                                      uint32_t& r3, uint32_t addr) {
    asm volatile("ldmatrix.sync.aligned.m8n8.x4.shared.b16 {%0,%1,%2,%3}, [%4];"
                 : "=r"(r0), "=r"(r1), "=r"(r2), "=r"(r3) : "r"(addr));
}
__device__ __forceinline__ void ldsm4t(uint32_t& r0, uint32_t& r1, uint32_t& r2,
                                       uint32_t& r3, uint32_t addr) {
    asm volatile("ldmatrix.sync.aligned.m8n8.x4.trans.shared.b16 {%0,%1,%2,%3}, [%4];"
                 : "=r"(r0), "=r"(r1), "=r"(r2), "=r"(r3) : "r"(addr));
}
__device__ __forceinline__ void mma16816(float* c, uint32_t a0, uint32_t a1,
                                         uint32_t a2, uint32_t a3,
                                         uint32_t b0, uint32_t b1) {
    asm volatile(
        "mma.sync.aligned.m16n8k16.row.col.f32.f16.f16.f32 "
        "{%0,%1,%2,%3}, {%4,%5,%6,%7}, {%8,%9}, {%0,%1,%2,%3};"
        : "+f"(c[0]), "+f"(c[1]), "+f"(c[2]), "+f"(c[3])
        : "r"(a0), "r"(a1), "r"(a2), "r"(a3), "r"(b0), "r"(b1));
}
// split two floats into packed f16x2 hi + lo
__device__ __forceinline__ uint32_t hsplit2(float a, float b, uint32_t& lo) {
    __half ha = __float2half_rn(a), hb = __float2half_rn(b);
    __half la = __float2half_rn(a - __half2float(ha));
    __half lb = __float2half_rn(b - __half2float(hb));
    __half2 H = __halves2half2(ha, hb);
    __half2 L = __halves2half2(la, lb);
    lo = *(uint32_t*)&L;
    return *(uint32_t*)&H;
}
// pack two floats into f16x2 (hi only)
__device__ __forceinline__ uint32_t hpack2(float a, float b) {
    __half2 H = __halves2half2(__float2half_rn(a), __float2half_rn(b));
    return *(uint32_t*)&H;
}
// fast exp2 via degree-6 poly (rel err ~1.6e-5) — FMA pipe, no MUFU
__device__ __forceinline__ float fexp2(float x) {
    x = fmaxf(x, -120.f);
    float xi = floorf(x);
    float f = x - xi;
    float p = 1.54035304e-4f;
    p = fmaf(p, f, 1.33335581e-3f);
    p = fmaf(p, f, 9.61812911e-3f);
    p = fmaf(p, f, 5.55041087e-2f);
    p = fmaf(p, f, 2.40226507e-1f);
    p = fmaf(p, f, 6.93147181e-1f);
    p = fmaf(p, f, 1.0f);
    return p * __int_as_float(((int)xi + 127) << 23);
}

// ---------------------------------------------------------------------------
// convw + x-convert prologue: x fp32 -> fp16 hi (A-side, no lo), then
// transpose + split weights to fp16 hi/lo (B-side).
// grid (16,16,4), block (32,8).
// ---------------------------------------------------------------------------
__global__ __launch_bounds__(256) void convw_kernel(
    const float* __restrict__ x,
    const float* __restrict__ wq, const float* __restrict__ wk,
    const float* __restrict__ wv, const float* __restrict__ wd)
{
    const int t = threadIdx.y * 32 + threadIdx.x;
    {
        const size_t gid = ((size_t)blockIdx.z * 16 + blockIdx.y) * 16 + blockIdx.x;
        const size_t NV = (size_t)MT * Dmod / 4;
        for (size_t v = gid * 256 + t; v < NV; v += (size_t)1024 * 256) {
            size_t i = v * 4;
            float4 val = *(const float4*)(x + i);
            *(uint32_t*)(g_xhi + i)     = hpack2(val.x, val.y);
            *(uint32_t*)(g_xhi + i + 2) = hpack2(val.z, val.w);
        }
    }
    const int z = blockIdx.z;
    const float* w = (z == 0) ? wq : (z == 1) ? wk : (z == 2) ? wv : wd;
    __shared__ float tile[32][33];
    const int k0 = blockIdx.x * 32, n0 = blockIdx.y * 32;
    const int tx = threadIdx.x, ty = threadIdx.y;
#pragma unroll
    for (int i = 0; i < 4; i++)
        tile[ty + i * 8][tx] = w[(size_t)(k0 + ty + i * 8) * Dmod + n0 + tx];
    __syncthreads();
#pragma unroll
    for (int i = 0; i < 4; i++) {
        float xv = tile[tx][ty + i * 8];
        __half h = __float2half_rn(xv);
        size_t o = (size_t)z * Dmod * Dmod + (size_t)(n0 + ty + i * 8) * Dmod + k0 + tx;
        g_whi[o] = h;
        g_wlo[o] = __float2half_rn(xv - __half2float(h));
    }
}

// ---------------------------------------------------------------------------
// fp16 asymmetric-split GEMM: C(128x128) = A(Mx512) @ W(512x512)
// A: hi only; B: hi+lo. Two MMA passes (hh + hl). R10 pipeline structure.
// smem stage: Ahi 0 (10240), Bhi 10240, Blo 20480; stride 30720; 2 stages.
// mode 0 folds E/F fp32->fp16 conversion prologue (consumed later by proj).
// ---------------------------------------------------------------------------
__device__ __forceinline__ void issue_chunk(
    const __half* __restrict__ Ahi,
    const __half* __restrict__ Bhi, const __half* __restrict__ Blo,
    uint32_t sb, int stage, int c, int t, int rowBase, int colBase)
{
    const int k0 = c * 32;
#pragma unroll
    for (int u = 0; u < 2; u++) {
        int id = t + u * 256;
        int row = id >> 2, k8 = id & 3;
        size_t gA = (size_t)(rowBase + row) * Dmod + k0 + k8 * 8;
        size_t gB = (size_t)(colBase + row) * Dmod + k0 + k8 * 8;
        uint32_t so = sb + stage * 30720 + row * 80 + k8 * 16;
        cpa16(so + 0,     Ahi + gA);
        cpa16(so + 10240, Bhi + gB);
        cpa16(so + 20480, Blo + gB);
    }
    asm volatile("cp.async.commit_group;" ::: "memory");
}

__global__ __launch_bounds__(256) void gemm_kernel(
    const __half* __restrict__ Ahi,
    const float* __restrict__ bias, float* __restrict__ dOut,
    const float* __restrict__ Esrc, const float* __restrict__ Fsrc, int mode)
{
    extern __shared__ __align__(128) char smx[];
    const uint32_t sb = smem_u32(smx);
    const int t = threadIdx.x;
    const int lane = t & 31, wid = t >> 5;
    const int warpM = wid & 3, warpN = wid >> 2;
    const int z   = (mode == 0) ? (blockIdx.x >> 2) : 3;
    const int col = (mode == 0) ? (blockIdx.x & 3) : blockIdx.x;
    const int rowBase = blockIdx.y * 128;
    const int colBase = col * 128;
    const __half* Bhi = g_whi + (size_t)z * Dmod * Dmod;
    const __half* Blo = g_wlo + (size_t)z * Dmod * Dmod;

    // ---- folded E/F fp16 conversion prologue (mode 0 only) ----
    if (mode == 0) {
        const size_t NV = (size_t)Hh * Nseq * Rr / 4;
        const size_t gsz = (size_t)12 * gridDim.y * 256;
        for (size_t v = (size_t)(blockIdx.y * 12 + blockIdx.x) * 256 + t;
             v < 2 * NV; v += gsz) {
            const float* src;
            __half* hi;
            size_t i;
            if (v < NV) { src = Esrc; hi = g_ehi; i = v * 4; }
            else        { src = Fsrc; hi = g_fhi; i = (v - NV) * 4; }
            float4 val = *(const float4*)(src + i);
            *(uint32_t*)(hi + i)     = hpack2(val.x, val.y);
            *(uint32_t*)(hi + i + 2) = hpack2(val.z, val.w);
        }
    }

    float acc[2][8][4];
#pragma unroll
    for (int mi = 0; mi < 2; mi++)
#pragma unroll
        for (int nf = 0; nf < 8; nf++)
#pragma unroll
            for (int j = 0; j < 4; j++) acc[mi][nf][j] = 0.f;

    issue_chunk(Ahi, Bhi, Blo, sb, 0, 0, t, rowBase, colBase);

    for (int c = 0; c < 16; c++) {
        if (c < 15) {
            issue_chunk(Ahi, Bhi, Blo, sb, (c + 1) & 1, c + 1, t, rowBase, colBase);
            asm volatile("cp.async.wait_group 1;" ::: "memory");
        } else {
            asm volatile("cp.async.wait_group 0;" ::: "memory");
        }
        __syncthreads();

        const uint32_t sA = sb + (c & 1) * 30720;
#pragma unroll
        for (int kk = 0; kk < 2; kk++) {
            uint32_t ahi[2][4], bhi[16], blo[16];
#pragma unroll
            for (int mi = 0; mi < 2; mi++) {
                int row = warpM * 32 + mi * 16 + (lane & 15);
                int colk = kk * 16 + (lane >> 4) * 8;
                uint32_t ao = row * 80 + colk * 2;
                ldsm4(ahi[mi][0], ahi[mi][1], ahi[mi][2], ahi[mi][3], sA + ao);
            }
#pragma unroll
            for (int g = 0; g < 4; g++) {
                int row = warpN * 64 + g * 16 + (lane & 7) + (lane >> 4) * 8;
                int colk = kk * 16 + ((lane >> 3) & 1) * 8;
                uint32_t bo = row * 80 + colk * 2;
                ldsm4(bhi[g * 4], bhi[g * 4 + 1], bhi[g * 4 + 2], bhi[g * 4 + 3],
                      sA + 10240 + bo);
                ldsm4(blo[g * 4], blo[g * 4 + 1], blo[g * 4 + 2], blo[g * 4 + 3],
                      sA + 20480 + bo);
            }
#pragma unroll
            for (int mi = 0; mi < 2; mi++)
#pragma unroll
                for (int nf = 0; nf < 8; nf++) {
                    int g = nf >> 1, j = nf & 1;
                    mma16816(acc[mi][nf], ahi[mi][0], ahi[mi][1], ahi[mi][2], ahi[mi][3],
                             bhi[g * 4 + j * 2], bhi[g * 4 + j * 2 + 1]);
                    mma16816(acc[mi][nf], ahi[mi][0], ahi[mi][1], ahi[mi][2], ahi[mi][3],
                             blo[g * 4 + j * 2], blo[g * 4 + j * 2 + 1]);
                }
        }
        __syncthreads();
    }

    const int r0base = rowBase + warpM * 32 + (lane >> 2);
    if (mode == 0) {
        // q: hi only (A-side downstream). k/v: hi+lo (B-side in proj).
        __half* oh = (z == 0) ? g_qhi : (z == 1) ? g_khi : g_vhi;
        __half* ol = (z == 1) ? g_klo : g_vlo;
        const bool wantLo = (z != 0);
        const int h = (colBase + warpN * 64) >> 6;
#pragma unroll
        for (int mi = 0; mi < 2; mi++) {
            int r0 = r0base + mi * 16;
            int bb = r0 >> 12, n = r0 & 4095;
            size_t rb0 = ((size_t)(bb * Hh + h) * Nseq + n) * DP;
            size_t rb1 = rb0 + 8 * DP;
#pragma unroll
            for (int nf = 0; nf < 8; nf++) {
                int d = nf * 8 + (lane & 3) * 2;
                uint32_t lo0, lo1;
                uint32_t hi0 = hsplit2(acc[mi][nf][0], acc[mi][nf][1], lo0);
                uint32_t hi1 = hsplit2(acc[mi][nf][2], acc[mi][nf][3], lo1);
                *(uint32_t*)(oh + rb0 + d) = hi0;
                *(uint32_t*)(oh + rb1 + d) = hi1;
                if (wantLo) {
                    *(uint32_t*)(ol + rb0 + d) = lo0;
                    *(uint32_t*)(ol + rb1 + d) = lo1;
                }
            }
        }
    } else {
        const int col0 = colBase + warpN * 64;
#pragma unroll
        for (int mi = 0; mi < 2; mi++) {
            int r0 = r0base + mi * 16;
            float* p0 = dOut + (size_t)r0 * Dmod + col0;
            float* p1 = p0 + 8 * Dmod;
#pragma unroll
            for (int nf = 0; nf < 8; nf++) {
                int d = nf * 8 + (lane & 3) * 2;
                float2 bi = *(const float2*)(bias + col0 + d);
                *(float2*)(p0 + d) = make_float2(acc[mi][nf][0] + bi.x,
                                                 acc[mi][nf][1] + bi.y);
                *(float2*)(p1 + d) = make_float2(acc[mi][nf][2] + bi.x,
                                                 acc[mi][nf][3] + bi.y);
            }
        }
    }
}

// ---------------------------------------------------------------------------
// proj: kp/vp[r,d] = sum_n E/F[h,n,r] * k/v[bh,n,d].
// A = E (hi only), B = K/V (hi+lo). Two MMA passes.
// smem stage: Ehi 0 (16896), Khi 16896 (4608), Klo 21504 (4608); PSTG 26112.
// ---------------------------------------------------------------------------
#define PEHI 0
#define PKHI 16896
#define PKLO 21504
#define PSTG 26112

__global__ __launch_bounds__(256) void proj_kernel()
{
    extern __shared__ __align__(128) char smx[];
    const uint32_t sb = smem_u32(smx);
    const int t = threadIdx.x, lane = t & 31, wid = t >> 5;
    const int warpM = wid & 3, warpN = wid >> 2;
    const int bh = blockIdx.x & 63, ef = blockIdx.x >> 6;
    const int ks = blockIdx.y;
    const int h = bh & 7;

    const __half* Eh = (ef ? g_fhi : g_ehi) + (size_t)h * Nseq * Rr;
    const __half* Kh = (ef ? g_vhi : g_khi) + (size_t)bh * Nseq * DP;
    const __half* Kl = (ef ? g_vlo : g_klo) + (size_t)bh * Nseq * DP;
    float* part = g_part + (((size_t)ef * 4 + ks) * 64 + bh) * 16384;

    const int nBase = ks * 1024;
    const int r0 = warpM * 64, d0 = warpN * 32;

    float acc[16][4];
#pragma unroll
    for (int i = 0; i < 16; i++)
#pragma unroll
        for (int j = 0; j < 4; j++) acc[i][j] = 0.f;

    auto issue = [&](int stage, int c) {
        const int n0 = nBase + c * 32;
        const uint32_t so = sb + stage * PSTG;
#pragma unroll
        for (int u = 0; u < 4; u++) {
            int id = u * 256 + t;
            int row = id >> 5, seg = id & 31;
            cpa16(so + PEHI + row * 528 + seg * 16, Eh + (size_t)(n0 + row) * Rr + seg * 8);
        }
        {
            int row = t >> 3, seg = t & 7;
            cpa16(so + PKHI + row * 144 + seg * 16, Kh + (size_t)(n0 + row) * DP + seg * 8);
            cpa16(so + PKLO + row * 144 + seg * 16, Kl + (size_t)(n0 + row) * DP + seg * 8);
        }
        asm volatile("cp.async.commit_group;" ::: "memory");
    };

    issue(0, 0);
    for (int c = 0; c < 32; c++) {
        if (c < 31) {
            issue((c + 1) & 1, c + 1);
            asm volatile("cp.async.wait_group 1;" ::: "memory");
        } else {
            asm volatile("cp.async.wait_group 0;" ::: "memory");
        }
        __syncthreads();

        const uint32_t st = sb + (c & 1) * PSTG;
#pragma unroll
        for (int kk = 0; kk < 2; kk++) {
            uint32_t ah[4][4];
            const int krA = kk * 16 + (lane & 7) + ((lane >> 4) & 1) * 8;
#pragma unroll
            for (int mf = 0; mf < 4; mf++) {
                uint32_t off = krA * 528 + (r0 + mf * 16 + ((lane >> 3) & 1) * 8) * 2;
                ldsm4t(ah[mf][0], ah[mf][1], ah[mf][2], ah[mf][3], st + PEHI + off);
            }
            const int krB = kk * 16 + (lane & 7) + ((lane >> 3) & 1) * 8;
#pragma unroll
            for (int g2 = 0; g2 < 2; g2++) {
                uint32_t off = krB * 144 + (d0 + g2 * 16 + ((lane >> 4) & 1) * 8) * 2;
                uint32_t b0, b1, b2, b3, l0, l1, l2, l3;
                ldsm4t(b0, b1, b2, b3, st + PKHI + off);
                ldsm4t(l0, l1, l2, l3, st + PKLO + off);
#pragma unroll
                for (int mf = 0; mf < 4; mf++) {
                    float* c0 = acc[mf * 4 + g2 * 2];
                    float* c1 = acc[mf * 4 + g2 * 2 + 1];
                    mma16816(c0, ah[mf][0], ah[mf][1], ah[mf][2], ah[mf][3], b0, b1);
                    mma16816(c1, ah[mf][0], ah[mf][1], ah[mf][2], ah[mf][3], b2, b3);
                    mma16816(c0, ah[mf][0], ah[mf][1], ah[mf][2], ah[mf][3], l0, l1);
                    mma16816(c1, ah[mf][0], ah[mf][1], ah[mf][2], ah[mf][3], l2, l3);
                }
            }
        }
        __syncthreads();
    }

#pragma unroll
    for (int mf = 0; mf < 4; mf++) {
        int r = r0 + mf * 16 + (lane >> 2);
#pragma unroll
        for (int f = 0; f < 4; f++) {
            int d = d0 + f * 8 + (lane & 3) * 2;
            *(float2*)(part + r * 64 + d) =
                make_float2(acc[mf * 4 + f][0], acc[mf * 4 + f][1]);
            *(float2*)(part + (r + 8) * 64 + d) =
                make_float2(acc[mf * 4 + f][2], acc[mf * 4 + f][3]);
        }
    }
}

// reduce 4 K-split partials -> fp16 hi/lo kp/vp (B-side). grid (1024, 2).
__global__ __launch_bounds__(256) void reduce_kernel()
{
    const int ef = blockIdx.y;
    size_t base = ((size_t)blockIdx.x * 256 + threadIdx.x) * 4;
    const float* p = g_part + (size_t)ef * 4194304 + base;
    float4 s0 = *(const float4*)(p);
    float4 s1 = *(const float4*)(p + 1048576);
    float4 s2 = *(const float4*)(p + 2097152);
    float4 s3 = *(const float4*)(p + 3145728);
    float a = s0.x + s1.x + s2.x + s3.x;
    float b = s0.y + s1.y + s2.y + s3.y;
    float c = s0.z + s1.z + s2.z + s3.z;
    float d = s0.w + s1.w + s2.w + s3.w;
    __half* hi = ef ? g_vphi : g_kphi;
    __half* lo = ef ? g_vplo : g_kplo;
    uint32_t l0, l1;
    uint32_t h0 = hsplit2(a, b, l0);
    uint32_t h1 = hsplit2(c, d, l1);
    *(uint32_t*)(hi + base)     = h0;
    *(uint32_t*)(hi + base + 2) = h1;
    *(uint32_t*)(lo + base)     = l0;
    *(uint32_t*)(lo + base + 2) = l1;
}

// ---------------------------------------------------------------------------
// attn: per block one (b,h) + FOUR 128-row Q tiles (pipeline from R13).
// A-sides (Q, P) fp16 hi only; B-sides (kp, vp) hi+lo. Two MMA passes each.
// smem: Qhi 0 (18432), kphi 18432, kplo 55296, vphi 92160, vplo 129024;
// total 165888 B.
// ---------------------------------------------------------------------------
#define AQHI 0
#define AKPHI 18432
#define AKPLO 55296
#define AVPHI 92160
#define AVPLO 129024
#define NTILE 4

__global__ __launch_bounds__(256) void attn_kernel()
{
    extern __shared__ __align__(128) char smx[];
    const uint32_t sb = smem_u32(smx);
    const int t = threadIdx.x, lane = t & 31, w = t >> 5;
    const int bh = blockIdx.x;
    const int tileBase = blockIdx.y * NTILE;

    const __half* kh = g_kphi + (size_t)bh * Rr * DP;
    const __half* kl = g_kplo + (size_t)bh * Rr * DP;
    const __half* vh = g_vphi + (size_t)bh * Rr * DP;
    const __half* vl = g_vplo + (size_t)bh * Rr * DP;

    auto loadQ = [&](int tile) {
        const __half* qh = g_qhi + ((size_t)bh * Nseq + tile * 128) * DP;
#pragma unroll
        for (int u = 0; u < 4; u++) {
            int id = u * 256 + t, row = id >> 3, seg = id & 7;
            cpa16(sb + AQHI + row * 144 + seg * 16, qh + row * 64 + seg * 8);
        }
        asm volatile("cp.async.commit_group;" ::: "memory");
    };

    // group0: kp + Q(tile0); group1: vp
#pragma unroll
    for (int u = 0; u < 8; u++) {
        int id = u * 256 + t, row = id >> 3, seg = id & 7;
        cpa16(sb + AKPHI + row * 144 + seg * 16, kh + row * 64 + seg * 8);
        cpa16(sb + AKPLO + row * 144 + seg * 16, kl + row * 64 + seg * 8);
    }
    {
        const __half* qh = g_qhi + ((size_t)bh * Nseq + tileBase * 128) * DP;
#pragma unroll
        for (int u = 0; u < 4; u++) {
            int id = u * 256 + t, row = id >> 3, seg = id & 7;
            cpa16(sb + AQHI + row * 144 + seg * 16, qh + row * 64 + seg * 8);
        }
    }
    asm volatile("cp.async.commit_group;" ::: "memory");
#pragma unroll
    for (int u = 0; u < 8; u++) {
        int id = u * 256 + t, row = id >> 3, seg = id & 7;
        cpa16(sb + AVPHI + row * 144 + seg * 16, vh + row * 64 + seg * 8);
        cpa16(sb + AVPLO + row * 144 + seg * 16, vl + row * 64 + seg * 8);
    }
    asm volatile("cp.async.commit_group;" ::: "memory");

    const int m0 = w * 16;
    const float C = 0.125f * 1.4426950408889634f;
    const int b = bh >> 3, h = bh & 7;

    for (int tt = 0; tt < NTILE; tt++) {
        const int tile = tileBase + tt;
        if (tt == 0) {
            asm volatile("cp.async.wait_group 1;" ::: "memory");
        } else {
            asm volatile("cp.async.wait_group 0;" ::: "memory");
        }
        __syncthreads();

        // ---- GEMM1: scores[16][256] ----
        float c[32][4];
#pragma unroll
        for (int i = 0; i < 32; i++)
#pragma unroll
            for (int j = 0; j < 4; j++) c[i][j] = 0.f;

#pragma unroll
        for (int kk = 0; kk < 4; kk++) {
            uint32_t ah0, ah1, ah2, ah3;
            {
                uint32_t ar = (m0 + (lane & 15)) * 144 + (kk * 16 + (lane >> 4) * 8) * 2;
                ldsm4(ah0, ah1, ah2, ah3, sb + AQHI + ar);
            }
#pragma unroll
            for (int nb = 0; nb < 16; nb++) {
                uint32_t br = (nb * 16 + (lane & 7) + ((lane >> 4) & 1) * 8) * 144
                            + (kk * 16 + ((lane >> 3) & 1) * 8) * 2;
                uint32_t b0, b1, b2, b3, l0, l1, l2, l3;
                ldsm4(b0, b1, b2, b3, sb + AKPHI + br);
                ldsm4(l0, l1, l2, l3, sb + AKPLO + br);
                mma16816(c[2 * nb],     ah0, ah1, ah2, ah3, b0, b1);
                mma16816(c[2 * nb + 1], ah0, ah1, ah2, ah3, b2, b3);
                mma16816(c[2 * nb],     ah0, ah1, ah2, ah3, l0, l1);
                mma16816(c[2 * nb + 1], ah0, ah1, ah2, ah3, l2, l3);
            }
        }

        // ---- softmax ----
        float mx0 = -1e30f, mx1 = -1e30f;
#pragma unroll
        for (int f = 0; f < 32; f++) {
            mx0 = fmaxf(mx0, fmaxf(c[f][0], c[f][1]));
            mx1 = fmaxf(mx1, fmaxf(c[f][2], c[f][3]));
        }
        mx0 = fmaxf(mx0, __shfl_xor_sync(0xffffffffu, mx0, 1));
        mx0 = fmaxf(mx0, __shfl_xor_sync(0xffffffffu, mx0, 2));
        mx1 = fmaxf(mx1, __shfl_xor_sync(0xffffffffu, mx1, 1));
        mx1 = fmaxf(mx1, __shfl_xor_sync(0xffffffffu, mx1, 2));
        float s0 = 0.f, s1 = 0.f;
#pragma unroll
        for (int f = 0; f < 32; f++) {
            c[f][0] = fexp2((c[f][0] - mx0) * C);
            c[f][1] = fexp2((c[f][1] - mx0) * C);
            c[f][2] = fexp2((c[f][2] - mx1) * C);
            c[f][3] = fexp2((c[f][3] - mx1) * C);
            s0 += c[f][0] + c[f][1];
            s1 += c[f][2] + c[f][3];
        }
        s0 += __shfl_xor_sync(0xffffffffu, s0, 1);
        s0 += __shfl_xor_sync(0xffffffffu, s0, 2);
        s1 += __shfl_xor_sync(0xffffffffu, s1, 1);
        s1 += __shfl_xor_sync(0xffffffffu, s1, 2);
        const float inv0 = 1.f / s0, inv1 = 1.f / s1;

        // pack P as fp16 A-fragments (hi only)
        uint32_t phi[64];
#pragma unroll
        for (int f = 0; f < 32; f++) {
            int base = (f >> 1) * 4 + (f & 1) * 2;
            phi[base]     = hpack2(c[f][0] * inv0, c[f][1] * inv0);
            phi[base + 1] = hpack2(c[f][2] * inv1, c[f][3] * inv1);
        }

        __syncthreads();
        if (tt + 1 < NTILE) loadQ(tile + 1);
        if (tt == 0) {
            asm volatile("cp.async.wait_group 1;" ::: "memory");
            __syncthreads();
        }

        // ---- GEMM2: out[16][64] = P @ vp ----
        float o[8][4];
#pragma unroll
        for (int i = 0; i < 8; i++)
#pragma unroll
            for (int j = 0; j < 4; j++) o[i][j] = 0.f;

#pragma unroll
        for (int ks = 0; ks < 16; ks++) {
            uint32_t A0 = phi[ks * 4], A1 = phi[ks * 4 + 1];
            uint32_t A2 = phi[ks * 4 + 2], A3 = phi[ks * 4 + 3];
            const int krB = ks * 16 + (lane & 7) + ((lane >> 3) & 1) * 8;
#pragma unroll
            for (int g2 = 0; g2 < 4; g2++) {
                uint32_t off = krB * 144 + (g2 * 16 + ((lane >> 4) & 1) * 8) * 2;
                uint32_t b0, b1, b2, b3, l0, l1, l2, l3;
                ldsm4t(b0, b1, b2, b3, sb + AVPHI + off);
                ldsm4t(l0, l1, l2, l3, sb + AVPLO + off);
                mma16816(o[g2 * 2],     A0, A1, A2, A3, b0, b1);
                mma16816(o[g2 * 2 + 1], A0, A1, A2, A3, b2, b3);
                mma16816(o[g2 * 2],     A0, A1, A2, A3, l0, l1);
                mma16816(o[g2 * 2 + 1], A0, A1, A2, A3, l2, l3);
            }
        }

        // ---- epilogue: fp16 concat (A-side of dense, hi only) ----
        const int n0 = tile * 128 + m0 + (lane >> 2);
#pragma unroll
        for (int f = 0; f < 8; f++) {
            int d = f * 8 + (lane & 3) * 2;
            size_t i0 = (size_t)(b * Nseq + n0) * Dmod + h * 64 + d;
            size_t i1 = i0 + (size_t)8 * Dmod;
            *(uint32_t*)(g_chi + i0) = hpack2(o[f][0], o[f][1]);
            *(uint32_t*)(g_chi + i1) = hpack2(o[f][2], o[f][3]);
        }
    }
}

// ---------------------------------------------------------------------------
extern "C" void kernel_launch(void* const* d_in, const int* in_sizes, int n_in,
                              void* d_out, int out_size)
{
    const float* x  = (const float*)d_in[0];
    const float* wq = (const float*)d_in[1];
    const float* wk = (const float*)d_in[2];
    const float* wv = (const float*)d_in[3];
    const float* E  = (const float*)d_in[4];
    const float* F  = (const float*)d_in[5];
    const float* wd = (const float*)d_in[6];
    const float* bd = (const float*)d_in[7];
    float* out = (float*)d_out;

    __half *xhi, *chi;
    cudaGetSymbolAddress((void**)&xhi, g_xhi);
    cudaGetSymbolAddress((void**)&chi, g_chi);

    cudaFuncSetAttribute(gemm_kernel,
                         cudaFuncAttributeMaxDynamicSharedMemorySize, 61440);
    cudaFuncSetAttribute(proj_kernel,
                         cudaFuncAttributeMaxDynamicSharedMemorySize, 52224);
    cudaFuncSetAttribute(attn_kernel,
                         cudaFuncAttributeMaxDynamicSharedMemorySize, 165888);

    // x fp16 convert + weight transpose/split in one launch
    convw_kernel<<<dim3(16, 16, 4), dim3(32, 8)>>>(x, wq, wk, wv, wd);

    // QKV (A = x hi; B = w hi+lo); E/F fp16 convert folded as prologue
    gemm_kernel<<<dim3(12, MT / 128), 256, 61440>>>(xhi, nullptr, nullptr, E, F, 0);

    // low-rank projections -> partials -> kp/vp hi/lo
    proj_kernel<<<dim3(128, 4), 256, 52224>>>();
    reduce_kernel<<<dim3(1024, 2), 256>>>();

    // fused attention -> fp16 concat
    attn_kernel<<<dim3(BH, Nseq / 128 / NTILE), 256, 165888>>>();

    // output dense (A = concat hi; B = wd hi+lo)
    gemm_kernel<<<dim3(4, MT / 128), 256, 61440>>>(chi, bd, out, nullptr, nullptr, 1);
}